// round 3
// baseline (speedup 1.0000x reference)
#include <cuda_runtime.h>
#include <cstdint>

#define B_ 64
#define T_ 512
#define I_ 512
#define H_ 1024

// ---------------- scratch: only the tiny h double-buffer (512 KB) ----------------
__device__ float g_h[2][B_ * H_];

// ---------------- init: zero h0 each launch (step 511 dirties buffer 0) ----------------
__global__ void init_h0_kernel() {
    int i = blockIdx.x * blockDim.x + threadIdx.x;
    if (i < B_ * H_) g_h[0][i] = 0.0f;
}

// ---------------- pre-GEMM: out[b][t][n] = sum_k x[b][t][k]*Wi[n][k] + bi[n] + bh[n] ----
// M = T*B = 32768 (m = t*64 + b), N = 1024, K = 512. 64x64 tile, 256 thr, 4x4/thread.
// Writes pre-activations directly into the output buffer (scan updates in-place).
__global__ __launch_bounds__(256) void gemm_pre_kernel(
    const float* __restrict__ x, const float* __restrict__ Wi,
    const float* __restrict__ bi, const float* __restrict__ bh,
    float* __restrict__ out)
{
    __shared__ float As[16][68];
    __shared__ float Bs[16][68];

    const int tid = threadIdx.x;
    const int tx = tid & 15;        // n sub-tile
    const int ty = tid >> 4;        // m sub-tile
    const int mbase = blockIdx.y * 64;
    const int nbase = blockIdx.x * 64;

    const int lrow = tid >> 2;          // 0..63
    const int lkq  = (tid & 3) * 4;     // 0,4,8,12

    const int m_l = mbase + lrow;
    // A row m -> x[b = m%64][t = m/64][:]
    const float* arow = x + (size_t)(m_l & 63) * (T_ * I_) + (size_t)(m_l >> 6) * I_;
    const float* brow = Wi + (size_t)(nbase + lrow) * I_;

    float acc[4][4];
#pragma unroll
    for (int i = 0; i < 4; i++)
#pragma unroll
        for (int j = 0; j < 4; j++) acc[i][j] = 0.0f;

    for (int k0 = 0; k0 < I_; k0 += 16) {
        float4 a4 = *(const float4*)(arow + k0 + lkq);
        float4 b4 = *(const float4*)(brow + k0 + lkq);
        __syncthreads();
        As[lkq + 0][lrow] = a4.x; As[lkq + 1][lrow] = a4.y;
        As[lkq + 2][lrow] = a4.z; As[lkq + 3][lrow] = a4.w;
        Bs[lkq + 0][lrow] = b4.x; Bs[lkq + 1][lrow] = b4.y;
        Bs[lkq + 2][lrow] = b4.z; Bs[lkq + 3][lrow] = b4.w;
        __syncthreads();
#pragma unroll
        for (int kk = 0; kk < 16; kk++) {
            float a0 = As[kk][ty * 4 + 0], a1 = As[kk][ty * 4 + 1];
            float a2 = As[kk][ty * 4 + 2], a3 = As[kk][ty * 4 + 3];
            float b0 = Bs[kk][tx * 4 + 0], b1 = Bs[kk][tx * 4 + 1];
            float b2 = Bs[kk][tx * 4 + 2], b3 = Bs[kk][tx * 4 + 3];
            acc[0][0] += a0 * b0; acc[0][1] += a0 * b1; acc[0][2] += a0 * b2; acc[0][3] += a0 * b3;
            acc[1][0] += a1 * b0; acc[1][1] += a1 * b1; acc[1][2] += a1 * b2; acc[1][3] += a1 * b3;
            acc[2][0] += a2 * b0; acc[2][1] += a2 * b1; acc[2][2] += a2 * b2; acc[2][3] += a2 * b3;
            acc[3][0] += a3 * b0; acc[3][1] += a3 * b1; acc[3][2] += a3 * b2; acc[3][3] += a3 * b3;
        }
    }

    const int n0 = nbase + tx * 4;
    float bias0 = bi[n0 + 0] + bh[n0 + 0];
    float bias1 = bi[n0 + 1] + bh[n0 + 1];
    float bias2 = bi[n0 + 2] + bh[n0 + 2];
    float bias3 = bi[n0 + 3] + bh[n0 + 3];
#pragma unroll
    for (int i = 0; i < 4; i++) {
        int m = mbase + ty * 4 + i;
        int b = m & 63;
        int t = m >> 6;
        float4 o;
        o.x = acc[i][0] + bias0; o.y = acc[i][1] + bias1;
        o.z = acc[i][2] + bias2; o.w = acc[i][3] + bias3;
        *(float4*)(out + (size_t)b * (T_ * H_) + (size_t)t * H_ + n0) = o;
    }
}

// ---------------- per-step scan: out[b][t][:] = relu(out[b][t][:] + hprev @ Wh^T) ------
// 128 blocks: block owns a j-tile of 8 (Wh rows staged in smem). thread = (1 b, 2 j).
// h double buffer lives in device globals, indexed by parity of t.
__global__ __launch_bounds__(256) void scan_step_kernel(
    const float* __restrict__ Wh,
    float* __restrict__ out,
    int t, int is_last)
{
    __shared__ float whs[8][1028];   // +4 pad: rows 4 banks apart
    const int tid = threadIdx.x;
    const int jbase = blockIdx.x * 8;

    // stage Wh rows jbase..jbase+7 (32 KB) from L2
    for (int idx = tid; idx < 2048; idx += 256) {
        int j = idx >> 8;
        int kq = (idx & 255) * 4;
        float4 v = *(const float4*)(Wh + (size_t)(jbase + j) * H_ + kq);
        *(float4*)&whs[j][kq] = v;
    }
    __syncthreads();

    const int b  = tid >> 2;     // 0..63
    const int jl = tid & 3;      // 0..3
    const int j0 = jl, j1 = jl + 4;

    const float* hrow = g_h[t & 1] + b * H_;
    float* hnext      = g_h[(t + 1) & 1];

    float acc0 = 0.0f, acc1 = 0.0f;
#pragma unroll 8
    for (int k = 0; k < H_; k += 4) {
        float4 h4 = *(const float4*)(hrow + k);
        float4 w0 = *(const float4*)&whs[j0][k];
        float4 w1 = *(const float4*)&whs[j1][k];
        acc0 += h4.x * w0.x; acc1 += h4.x * w1.x;
        acc0 += h4.y * w0.y; acc1 += h4.y * w1.y;
        acc0 += h4.z * w0.z; acc1 += h4.z * w1.z;
        acc0 += h4.w * w0.w; acc1 += h4.w * w1.w;
    }

    // in-place: read pre, write activated value back to the same slot
    float* orow = out + (size_t)b * (T_ * H_) + (size_t)t * H_ + jbase;
    float v0 = fmaxf(acc0 + orow[j0], 0.0f);
    float v1 = fmaxf(acc1 + orow[j1], 0.0f);
    orow[j0] = v0;
    orow[j1] = v1;

    const size_t hb = (size_t)b * H_ + jbase;
    hnext[hb + j0] = v0;
    hnext[hb + j1] = v1;
    if (is_last) {
        float* hid = out + (size_t)B_ * T_ * H_;
        hid[hb + j0] = v0;
        hid[hb + j1] = v1;
    }
}

// ---------------- launch: kernel launches only ----------------
extern "C" void kernel_launch(void* const* d_in, const int* in_sizes, int n_in,
                              void* d_out, int out_size)
{
    const float* x  = (const float*)d_in[0];
    const float* Wi = (const float*)d_in[1];
    const float* bi = (const float*)d_in[2];
    const float* Wh = (const float*)d_in[3];
    const float* bh = (const float*)d_in[4];
    float* out = (float*)d_out;

    init_h0_kernel<<<64, 1024>>>();
    dim3 grid_gemm(H_ / 64, (T_ * B_) / 64);   // (16, 512)
    gemm_pre_kernel<<<grid_gemm, 256>>>(x, Wi, bi, bh, out);

    for (int t = 0; t < T_; t++) {
        scan_step_kernel<<<128, 256>>>(Wh, out, t, t == T_ - 1);
    }
}